// round 4
// baseline (speedup 1.0000x reference)
#include <cuda_runtime.h>
#include <cstdint>

// ---------------- problem constants ----------------
#define B     4096
#define NS    26
#define DNS   13
#define D     16
#define V     100000
#define F     128
#define NN    39          // N = NS + DNS
#define DIN   429         // NS*D + DNS
#define D1    1024
#define D2    512
#define D3    256
#define MTOT  (B*D)       // 65536 rows for CIN GEMMs
#define K0    (NN*NN)     // 1521
#define K12   (F*NN)      // 4992
#define EPSBN 1e-5f

// ---------------- device scratch (static, allowed) ----------------
__device__ float g_x0[(size_t)MTOT * NN];        // x0 transposed: [(b,d)][n]
__device__ float g_y0[(size_t)MTOT * F];         // CIN layer outputs [(b,d)][f]
__device__ float g_y1[(size_t)MTOT * F];
__device__ float g_y2[(size_t)MTOT * F];
__device__ float g_Wt0[(size_t)K0  * F];         // W transposed [k][f]
__device__ float g_Wt1[(size_t)K12 * F];
__device__ float g_Wt2[(size_t)K12 * F];
__device__ float g_h0[(size_t)B * DIN];
__device__ float g_h1[(size_t)B * D1];
__device__ float g_h2[(size_t)B * D2];
__device__ float g_h3[(size_t)B * D3];
__device__ float g_p [(size_t)B * 3 * F];
__device__ float g_lin[B];

// ---------------- prep: gather embeddings, build x0 / h0 / linear part ----------------
__global__ void prep_kernel(const float* __restrict__ dense_x,
                            const int*   __restrict__ disc,
                            const float* __restrict__ lin_emb,
                            const float* __restrict__ emb_W,
                            const float* __restrict__ dense_W,
                            const float* __restrict__ dense_b,
                            const float* __restrict__ dense_proj)
{
    int b = blockIdx.x;
    int lane = threadIdx.x;          // 32 threads
    float linacc = 0.f;

    if (lane < NS) {
        int idx = disc[b * NS + lane];
        const float4* src = reinterpret_cast<const float4*>(
            emb_W + ((size_t)lane * V + (size_t)idx) * D);
        float e[16];
        #pragma unroll
        for (int j = 0; j < 4; j++) {
            float4 v = src[j];
            e[4*j+0] = v.x; e[4*j+1] = v.y; e[4*j+2] = v.z; e[4*j+3] = v.w;
        }
        #pragma unroll
        for (int j = 0; j < 16; j++) {
            g_h0[(size_t)b * DIN + lane * 16 + j] = e[j];
            g_x0[((size_t)(b * D + j)) * NN + lane] = e[j];
        }
        linacc += lin_emb[(size_t)lane * V + idx];
    }
    if (lane < DNS) {
        float v = dense_x[b * DNS + lane];
        g_h0[(size_t)b * DIN + NS * D + lane] = v;
        #pragma unroll
        for (int d = 0; d < D; d++)
            g_x0[((size_t)(b * D + d)) * NN + NS + lane] = v * dense_proj[lane * D + d];
        linacc += v * dense_W[lane];
    }
    #pragma unroll
    for (int o = 16; o; o >>= 1) linacc += __shfl_down_sync(0xffffffffu, linacc, o);
    if (lane == 0) g_lin[b] = linacc + dense_b[0];
}

// ---------------- W transpose: W[f][k] -> Wt[k][f] ----------------
__global__ void wtrans_kernel(const float* __restrict__ W0,
                              const float* __restrict__ W1,
                              const float* __restrict__ W2)
{
    int i = blockIdx.x * 256 + threadIdx.x;
    const int S0 = K0 * F, S1 = K12 * F;
    if (i < S0) { int k = i >> 7, f = i & 127; g_Wt0[i] = W0[f * K0 + k]; return; }
    i -= S0;
    if (i < S1) { int k = i >> 7, f = i & 127; g_Wt1[i] = W1[f * K12 + k]; return; }
    i -= S1;
    if (i < S1) { int k = i >> 7, f = i & 127; g_Wt2[i] = W2[f * K12 + k]; }
}

// ---------------- CIN GEMM: y[m][f] = sum_{c,n} xj[m][c]*x0[m][n]*Wt[c*39+n][f] ----
// Tile: 64 rows x 128 cols; 128 threads; each thread 8x8 register tile.
template<int C, bool SELF, int L>
__global__ void __launch_bounds__(128)
cin_gemm_kernel()
{
    constexpr int RS = 68;                               // padded smem row stride
    __shared__ float x0T[NN * RS];
    __shared__ float xjT[(SELF ? 1 : C) * RS];

    const float* __restrict__ xj = (L == 1) ? g_y0 : g_y1;      // unused if SELF
    const float* __restrict__ Wt = (L == 0) ? g_Wt0 : (L == 1) ? g_Wt1 : g_Wt2;
    float* __restrict__ y        = (L == 0) ? g_y0  : (L == 1) ? g_y1  : g_y2;

    int m0  = blockIdx.x * 64;
    int tid = threadIdx.x;

    // stage x0 tile transposed: x0T[n][r]
    for (int i = tid; i < 64 * NN; i += 128) {
        int r = i / NN, n = i - r * NN;
        x0T[n * RS + r] = g_x0[(size_t)(m0 + r) * NN + n];
    }
    if (!SELF) {
        for (int i = tid; i < 64 * C; i += 128) {
            int r = i >> 7, c = i & 127;                 // C == 128 here
            xjT[c * RS + r] = xj[(size_t)(m0 + r) * F + c];
        }
    }
    __syncthreads();

    int tx = tid & 15;          // 16 col-groups * 8 cols = 128
    int ty = tid >> 4;          // 8 row-groups * 8 rows  = 64

    float acc[8][8];
    #pragma unroll
    for (int r = 0; r < 8; r++)
        #pragma unroll
        for (int f = 0; f < 8; f++) acc[r][f] = 0.f;

    const float* wb = Wt + tx * 8;

    #pragma unroll 1
    for (int c = 0; c < C; c++) {
        float xjv[8];
        const float* xs = SELF ? &x0T[c * RS + ty * 8] : &xjT[c * RS + ty * 8];
        #pragma unroll
        for (int r = 0; r < 8; r++) xjv[r] = xs[r];

        const float* wc = wb + (size_t)c * (NN * F);
        #pragma unroll 3
        for (int n = 0; n < NN; n++) {
            float4 w0 = __ldg(reinterpret_cast<const float4*>(wc + n * F));
            float4 w1 = __ldg(reinterpret_cast<const float4*>(wc + n * F + 4));
            float wv[8] = {w0.x, w0.y, w0.z, w0.w, w1.x, w1.y, w1.z, w1.w};
            float x0v[8];
            const float* xp = &x0T[n * RS + ty * 8];
            #pragma unroll
            for (int r = 0; r < 8; r++) x0v[r] = xp[r];
            #pragma unroll
            for (int r = 0; r < 8; r++) {
                float a = xjv[r] * x0v[r];
                #pragma unroll
                for (int f = 0; f < 8; f++) acc[r][f] += a * wv[f];
            }
        }
    }

    #pragma unroll
    for (int r = 0; r < 8; r++) {
        int m = m0 + ty * 8 + r;
        float4 o0 = {acc[r][0], acc[r][1], acc[r][2], acc[r][3]};
        float4 o1 = {acc[r][4], acc[r][5], acc[r][6], acc[r][7]};
        *reinterpret_cast<float4*>(&y[(size_t)m * F + tx * 8])     = o0;
        *reinterpret_cast<float4*>(&y[(size_t)m * F + tx * 8 + 4]) = o1;
    }
}

// ---------------- p sums: p_l[b][f] = sum_d y_l[(b,d)][f] ----------------
__global__ void psum_kernel()
{
    int b = blockIdx.x, f = threadIdx.x;     // 128 threads
    float s0 = 0.f, s1 = 0.f, s2 = 0.f;
    #pragma unroll
    for (int d = 0; d < D; d++) {
        size_t idx = (size_t)(b * D + d) * F + f;
        s0 += g_y0[idx]; s1 += g_y1[idx]; s2 += g_y2[idx];
    }
    g_p[(size_t)b * (3 * F) + f]           = s0;
    g_p[(size_t)b * (3 * F) + F + f]       = s1;
    g_p[(size_t)b * (3 * F) + 2 * F + f]   = s2;
}

// ---------------- MLP GEMM + bias + BN(eval) + ReLU ----------------
// Tile 64x64, 128 threads, each 8 rows x 4 cols.
template<int STAGE>
__global__ void __launch_bounds__(128)
mlp_gemm_kernel(const float* __restrict__ W, const float* __restrict__ bias,
                const float* __restrict__ bng, const float* __restrict__ bnb)
{
    constexpr int K  = (STAGE == 0) ? DIN : (STAGE == 1) ? D1 : D2;
    constexpr int NO = (STAGE == 0) ? D1  : (STAGE == 1) ? D2 : D3;
    const float* __restrict__ A = (STAGE == 0) ? g_h0 : (STAGE == 1) ? g_h1 : g_h2;
    float* __restrict__ O       = (STAGE == 0) ? g_h1 : (STAGE == 1) ? g_h2 : g_h3;

    constexpr int RS = 68;
    __shared__ float AT[32 * RS];
    __shared__ float Wc[32 * 64];

    int m0 = blockIdx.y * 64, n0 = blockIdx.x * 64;
    int tid = threadIdx.x, tx = tid & 15, ty = tid >> 4;

    float acc[8][4];
    #pragma unroll
    for (int r = 0; r < 8; r++)
        #pragma unroll
        for (int f = 0; f < 4; f++) acc[r][f] = 0.f;

    for (int k0 = 0; k0 < K; k0 += 32) {
        for (int i = tid; i < 64 * 32; i += 128) {
            int r = i >> 5, k = i & 31;
            AT[k * RS + r] = (k0 + k < K) ? A[(size_t)(m0 + r) * K + k0 + k] : 0.f;
        }
        for (int i = tid; i < 32 * 64; i += 128) {
            int k = i >> 6, n = i & 63;
            Wc[k * 64 + n] = (k0 + k < K) ? W[(size_t)(k0 + k) * NO + n0 + n] : 0.f;
        }
        __syncthreads();

        #pragma unroll 4
        for (int k = 0; k < 32; k++) {
            float av[8];
            const float* ap = &AT[k * RS + ty * 8];
            #pragma unroll
            for (int r = 0; r < 8; r++) av[r] = ap[r];
            float4 w = *reinterpret_cast<const float4*>(&Wc[k * 64 + tx * 4]);
            float wv[4] = {w.x, w.y, w.z, w.w};
            #pragma unroll
            for (int r = 0; r < 8; r++)
                #pragma unroll
                for (int f = 0; f < 4; f++) acc[r][f] += av[r] * wv[f];
        }
        __syncthreads();
    }

    float rs = rsqrtf(1.f + EPSBN);
    int nb = n0 + tx * 4;
    float4 bi = *reinterpret_cast<const float4*>(&bias[nb]);
    float4 gg = *reinterpret_cast<const float4*>(&bng[nb]);
    float4 sh = *reinterpret_cast<const float4*>(&bnb[nb]);
    float s0 = gg.x * rs, s1 = gg.y * rs, s2 = gg.z * rs, s3 = gg.w * rs;

    #pragma unroll
    for (int r = 0; r < 8; r++) {
        int m = m0 + ty * 8 + r;
        float4 o;
        o.x = fmaxf(0.f, (acc[r][0] + bi.x) * s0 + sh.x);
        o.y = fmaxf(0.f, (acc[r][1] + bi.y) * s1 + sh.y);
        o.z = fmaxf(0.f, (acc[r][2] + bi.z) * s2 + sh.z);
        o.w = fmaxf(0.f, (acc[r][3] + bi.w) * s3 + sh.w);
        *reinterpret_cast<float4*>(&O[(size_t)m * NO + nb]) = o;
    }
}

// ---------------- final combine ----------------
__global__ void final_kernel(const float* __restrict__ Wout, const float* __restrict__ bout,
                             const float* __restrict__ cW,   const float* __restrict__ cb,
                             float* __restrict__ out)
{
    int b = blockIdx.x, tid = threadIdx.x;      // 128 threads
    float acc = 0.f;
    for (int i = tid; i < D3; i += 128)     acc += g_h3[(size_t)b * D3 + i] * Wout[i];
    for (int i = tid; i < 3 * F; i += 128)  acc += g_p[(size_t)b * (3 * F) + i] * cW[i];
    __shared__ float sm[4];
    #pragma unroll
    for (int o = 16; o; o >>= 1) acc += __shfl_down_sync(0xffffffffu, acc, o);
    if ((tid & 31) == 0) sm[tid >> 5] = acc;
    __syncthreads();
    if (tid == 0)
        out[b] = sm[0] + sm[1] + sm[2] + sm[3] + g_lin[b] + bout[0] + cb[0];
}

// ---------------- launch ----------------
extern "C" void kernel_launch(void* const* d_in, const int* in_sizes, int n_in,
                              void* d_out, int out_size)
{
    const float* dense_x    = (const float*)d_in[0];
    const int*   discrete_x = (const int*)  d_in[1];
    const float* lin_emb    = (const float*)d_in[2];
    const float* emb_W      = (const float*)d_in[3];
    const float* dense_W    = (const float*)d_in[4];
    const float* dense_b    = (const float*)d_in[5];
    const float* W1         = (const float*)d_in[6];
    const float* b1         = (const float*)d_in[7];
    const float* bn1_g      = (const float*)d_in[8];
    const float* bn1_b      = (const float*)d_in[9];
    const float* W2         = (const float*)d_in[10];
    const float* b2         = (const float*)d_in[11];
    const float* bn2_g      = (const float*)d_in[12];
    const float* bn2_b      = (const float*)d_in[13];
    const float* W3         = (const float*)d_in[14];
    const float* b3         = (const float*)d_in[15];
    const float* bn3_g      = (const float*)d_in[16];
    const float* bn3_b      = (const float*)d_in[17];
    const float* Wout       = (const float*)d_in[18];
    const float* bout       = (const float*)d_in[19];
    const float* dense_proj = (const float*)d_in[20];
    const float* cin_W0     = (const float*)d_in[21];
    const float* cin_W1     = (const float*)d_in[22];
    const float* cin_W2     = (const float*)d_in[23];
    const float* cin_out_W  = (const float*)d_in[24];
    const float* cin_out_b  = (const float*)d_in[25];
    float* out = (float*)d_out;

    prep_kernel<<<B, 32>>>(dense_x, discrete_x, lin_emb, emb_W,
                           dense_W, dense_b, dense_proj);

    int ttot = (K0 + 2 * K12) * F;
    wtrans_kernel<<<(ttot + 255) / 256, 256>>>(cin_W0, cin_W1, cin_W2);

    // CIN layers
    cin_gemm_kernel<NN, true,  0><<<MTOT / 64, 128>>>();
    cin_gemm_kernel<F,  false, 1><<<MTOT / 64, 128>>>();
    cin_gemm_kernel<F,  false, 2><<<MTOT / 64, 128>>>();
    psum_kernel<<<B, 128>>>();

    // DNN
    mlp_gemm_kernel<0><<<dim3(D1 / 64, B / 64), 128>>>(W1, b1, bn1_g, bn1_b);
    mlp_gemm_kernel<1><<<dim3(D2 / 64, B / 64), 128>>>(W2, b2, bn2_g, bn2_b);
    mlp_gemm_kernel<2><<<dim3(D3 / 64, B / 64), 128>>>(W3, b3, bn3_g, bn3_b);

    final_kernel<<<B, 128>>>(Wout, bout, cin_out_W, cin_out_b, out);
}

// round 6
// speedup vs baseline: 1.0547x; 1.0547x over previous
#include <cuda_runtime.h>
#include <cstdint>

// ---------------- problem constants ----------------
#define B     4096
#define NS    26
#define DNS   13
#define D     16
#define V     100000
#define F     128
#define NN    39          // N = NS + DNS
#define DIN   429         // NS*D + DNS
#define D1    1024
#define D2    512
#define D3    256
#define MTOT  (B*D)       // 65536 rows for CIN GEMMs
#define K0    (NN*NN)     // 1521
#define K12   (F*NN)      // 4992
#define EPSBN 1e-5f

// ---------------- device scratch (static, allowed) ----------------
__device__ float g_x0[(size_t)MTOT * NN];        // x0 transposed: [(b,d)][n]
__device__ float g_y0[(size_t)MTOT * F];         // CIN layer outputs [(b,d)][f]
__device__ float g_y1[(size_t)MTOT * F];
__device__ float g_y2[(size_t)MTOT * F];
__device__ float g_Wt0[(size_t)K0  * F];         // W transposed [k][f]
__device__ float g_Wt1[(size_t)K12 * F];
__device__ float g_Wt2[(size_t)K12 * F];
__device__ float g_h0[(size_t)B * DIN];
__device__ float g_h1[(size_t)B * D1];
__device__ float g_h2[(size_t)B * D2];
__device__ float g_h3[(size_t)B * D3];
__device__ float g_p [(size_t)B * 3 * F];
__device__ float g_lin[B];

// ---------------- prep: gather embeddings, build x0 / h0 / linear part ----------------
__global__ void prep_kernel(const float* __restrict__ dense_x,
                            const int*   __restrict__ disc,
                            const float* __restrict__ lin_emb,
                            const float* __restrict__ emb_W,
                            const float* __restrict__ dense_W,
                            const float* __restrict__ dense_b,
                            const float* __restrict__ dense_proj)
{
    int b = blockIdx.x;
    int lane = threadIdx.x;          // 32 threads
    float linacc = 0.f;

    if (lane < NS) {
        int idx = disc[b * NS + lane];
        const float4* src = reinterpret_cast<const float4*>(
            emb_W + ((size_t)lane * V + (size_t)idx) * D);
        float e[16];
        #pragma unroll
        for (int j = 0; j < 4; j++) {
            float4 v = src[j];
            e[4*j+0] = v.x; e[4*j+1] = v.y; e[4*j+2] = v.z; e[4*j+3] = v.w;
        }
        #pragma unroll
        for (int j = 0; j < 16; j++) {
            g_h0[(size_t)b * DIN + lane * 16 + j] = e[j];
            g_x0[((size_t)(b * D + j)) * NN + lane] = e[j];
        }
        linacc += lin_emb[(size_t)lane * V + idx];
    }
    if (lane < DNS) {
        float v = dense_x[b * DNS + lane];
        g_h0[(size_t)b * DIN + NS * D + lane] = v;
        #pragma unroll
        for (int d = 0; d < D; d++)
            g_x0[((size_t)(b * D + d)) * NN + NS + lane] = v * dense_proj[lane * D + d];
        linacc += v * dense_W[lane];
    }
    #pragma unroll
    for (int o = 16; o; o >>= 1) linacc += __shfl_down_sync(0xffffffffu, linacc, o);
    if (lane == 0) g_lin[b] = linacc + dense_b[0];
}

// ---------------- W transpose: W[f][k] -> Wt[k][f] ----------------
__global__ void wtrans_kernel(const float* __restrict__ W0,
                              const float* __restrict__ W1,
                              const float* __restrict__ W2)
{
    int i = blockIdx.x * 256 + threadIdx.x;
    const int S0 = K0 * F, S1 = K12 * F;
    if (i < S0) { int k = i >> 7, f = i & 127; g_Wt0[i] = W0[f * K0 + k]; return; }
    i -= S0;
    if (i < S1) { int k = i >> 7, f = i & 127; g_Wt1[i] = W1[f * K12 + k]; return; }
    i -= S1;
    if (i < S1) { int k = i >> 7, f = i & 127; g_Wt2[i] = W2[f * K12 + k]; }
}

// ---------------- CIN GEMM: y[m][f] = sum_{c,n} xj[m][c]*x0[m][n]*Wt[c*39+n][f] ----
// Tile: 64 rows x 128 cols; 128 threads; each thread 8x8 register tile.
template<int C, bool SELF, int L>
__global__ void __launch_bounds__(128)
cin_gemm_kernel()
{
    constexpr int RS = 68;                               // padded smem row stride
    __shared__ float x0T[NN * RS];
    __shared__ float xjT[(SELF ? 1 : C) * RS];

    const float* __restrict__ xj = (L == 1) ? g_y0 : g_y1;      // unused if SELF
    const float* __restrict__ Wt = (L == 0) ? g_Wt0 : (L == 1) ? g_Wt1 : g_Wt2;
    float* __restrict__ y        = (L == 0) ? g_y0  : (L == 1) ? g_y1  : g_y2;

    int m0  = blockIdx.x * 64;
    int tid = threadIdx.x;

    // stage x0 tile transposed: x0T[n][r]
    for (int i = tid; i < 64 * NN; i += 128) {
        int r = i / NN, n = i - r * NN;
        x0T[n * RS + r] = g_x0[(size_t)(m0 + r) * NN + n];
    }
    if (!SELF) {
        for (int i = tid; i < 64 * C; i += 128) {
            int r = i >> 7, c = i & 127;                 // C == 128 here
            xjT[c * RS + r] = xj[(size_t)(m0 + r) * F + c];
        }
    }
    __syncthreads();

    int tx = tid & 15;          // 16 col-groups * 8 cols = 128
    int ty = tid >> 4;          // 8 row-groups * 8 rows  = 64

    float acc[8][8];
    #pragma unroll
    for (int r = 0; r < 8; r++)
        #pragma unroll
        for (int f = 0; f < 8; f++) acc[r][f] = 0.f;

    const float* wb = Wt + tx * 8;

    #pragma unroll 1
    for (int c = 0; c < C; c++) {
        float xjv[8];
        const float* xs = SELF ? &x0T[c * RS + ty * 8] : &xjT[c * RS + ty * 8];
        #pragma unroll
        for (int r = 0; r < 8; r++) xjv[r] = xs[r];

        const float* wc = wb + (size_t)c * (NN * F);
        #pragma unroll 3
        for (int n = 0; n < NN; n++) {
            float4 w0 = __ldg(reinterpret_cast<const float4*>(wc + n * F));
            float4 w1 = __ldg(reinterpret_cast<const float4*>(wc + n * F + 4));
            float wv[8] = {w0.x, w0.y, w0.z, w0.w, w1.x, w1.y, w1.z, w1.w};
            float x0v[8];
            const float* xp = &x0T[n * RS + ty * 8];
            #pragma unroll
            for (int r = 0; r < 8; r++) x0v[r] = xp[r];
            #pragma unroll
            for (int r = 0; r < 8; r++) {
                float a = xjv[r] * x0v[r];
                #pragma unroll
                for (int f = 0; f < 8; f++) acc[r][f] += a * wv[f];
            }
        }
    }

    #pragma unroll
    for (int r = 0; r < 8; r++) {
        int m = m0 + ty * 8 + r;
        float4 o0 = {acc[r][0], acc[r][1], acc[r][2], acc[r][3]};
        float4 o1 = {acc[r][4], acc[r][5], acc[r][6], acc[r][7]};
        *reinterpret_cast<float4*>(&y[(size_t)m * F + tx * 8])     = o0;
        *reinterpret_cast<float4*>(&y[(size_t)m * F + tx * 8 + 4]) = o1;
    }
}

// ---------------- p sums: p_l[b][f] = sum_d y_l[(b,d)][f] ----------------
__global__ void psum_kernel()
{
    int b = blockIdx.x, f = threadIdx.x;     // 128 threads
    float s0 = 0.f, s1 = 0.f, s2 = 0.f;
    #pragma unroll
    for (int d = 0; d < D; d++) {
        size_t idx = (size_t)(b * D + d) * F + f;
        s0 += g_y0[idx]; s1 += g_y1[idx]; s2 += g_y2[idx];
    }
    g_p[(size_t)b * (3 * F) + f]           = s0;
    g_p[(size_t)b * (3 * F) + F + f]       = s1;
    g_p[(size_t)b * (3 * F) + 2 * F + f]   = s2;
}

// ---------------- MLP GEMM + bias + BN(eval) + ReLU ----------------
// Tile 64x64, 128 threads, each 8 rows x 4 cols.
template<int STAGE>
__global__ void __launch_bounds__(128)
mlp_gemm_kernel(const float* __restrict__ W, const float* __restrict__ bias,
                const float* __restrict__ bng, const float* __restrict__ bnb)
{
    constexpr int K  = (STAGE == 0) ? DIN : (STAGE == 1) ? D1 : D2;
    constexpr int NO = (STAGE == 0) ? D1  : (STAGE == 1) ? D2 : D3;
    const float* __restrict__ A = (STAGE == 0) ? g_h0 : (STAGE == 1) ? g_h1 : g_h2;
    float* __restrict__ O       = (STAGE == 0) ? g_h1 : (STAGE == 1) ? g_h2 : g_h3;

    constexpr int RS = 68;
    __shared__ float AT[32 * RS];
    __shared__ float Wc[32 * 64];

    int m0 = blockIdx.y * 64, n0 = blockIdx.x * 64;
    int tid = threadIdx.x, tx = tid & 15, ty = tid >> 4;

    float acc[8][4];
    #pragma unroll
    for (int r = 0; r < 8; r++)
        #pragma unroll
        for (int f = 0; f < 4; f++) acc[r][f] = 0.f;

    for (int k0 = 0; k0 < K; k0 += 32) {
        for (int i = tid; i < 64 * 32; i += 128) {
            int r = i >> 5, k = i & 31;
            AT[k * RS + r] = (k0 + k < K) ? A[(size_t)(m0 + r) * K + k0 + k] : 0.f;
        }
        for (int i = tid; i < 32 * 64; i += 128) {
            int k = i >> 6, n = i & 63;
            Wc[k * 64 + n] = (k0 + k < K) ? W[(size_t)(k0 + k) * NO + n0 + n] : 0.f;
        }
        __syncthreads();

        #pragma unroll 4
        for (int k = 0; k < 32; k++) {
            float av[8];
            const float* ap = &AT[k * RS + ty * 8];
            #pragma unroll
            for (int r = 0; r < 8; r++) av[r] = ap[r];
            float4 w = *reinterpret_cast<const float4*>(&Wc[k * 64 + tx * 4]);
            float wv[4] = {w.x, w.y, w.z, w.w};
            #pragma unroll
            for (int r = 0; r < 8; r++)
                #pragma unroll
                for (int f = 0; f < 4; f++) acc[r][f] += av[r] * wv[f];
        }
        __syncthreads();
    }

    float rs = rsqrtf(1.f + EPSBN);
    int nb = n0 + tx * 4;
    float4 bi = *reinterpret_cast<const float4*>(&bias[nb]);
    float4 gg = *reinterpret_cast<const float4*>(&bng[nb]);
    float4 sh = *reinterpret_cast<const float4*>(&bnb[nb]);
    float s0 = gg.x * rs, s1 = gg.y * rs, s2 = gg.z * rs, s3 = gg.w * rs;

    #pragma unroll
    for (int r = 0; r < 8; r++) {
        int m = m0 + ty * 8 + r;
        float4 o;
        o.x = fmaxf(0.f, (acc[r][0] + bi.x) * s0 + sh.x);
        o.y = fmaxf(0.f, (acc[r][1] + bi.y) * s1 + sh.y);
        o.z = fmaxf(0.f, (acc[r][2] + bi.z) * s2 + sh.z);
        o.w = fmaxf(0.f, (acc[r][3] + bi.w) * s3 + sh.w);
        *reinterpret_cast<float4*>(&O[(size_t)m * NO + nb]) = o;
    }
}

// ---------------- final combine ----------------
__global__ void final_kernel(const float* __restrict__ Wout, const float* __restrict__ bout,
                             const float* __restrict__ cW,   const float* __restrict__ cb,
                             float* __restrict__ out)
{
    int b = blockIdx.x, tid = threadIdx.x;      // 128 threads
    float acc = 0.f;
    for (int i = tid; i < D3; i += 128)     acc += g_h3[(size_t)b * D3 + i] * Wout[i];
    for (int i = tid; i < 3 * F; i += 128)  acc += g_p[(size_t)b * (3 * F) + i] * cW[i];
    __shared__ float sm[4];
    #pragma unroll
    for (int o = 16; o; o >>= 1) acc += __shfl_down_sync(0xffffffffu, acc, o);
    if ((tid & 31) == 0) sm[tid >> 5] = acc;
    __syncthreads();
    if (tid == 0)
        out[b] = sm[0] + sm[1] + sm[2] + sm[3] + g_lin[b] + bout[0] + cb[0];
}

// ---------------- launch ----------------
extern "C" void kernel_launch(void* const* d_in, const int* in_sizes, int n_in,
                              void* d_out, int out_size)
{
    const float* dense_x    = (const float*)d_in[0];
    const int*   discrete_x = (const int*)  d_in[1];
    const float* lin_emb    = (const float*)d_in[2];
    const float* emb_W      = (const float*)d_in[3];
    const float* dense_W    = (const float*)d_in[4];
    const float* dense_b    = (const float*)d_in[5];
    const float* W1         = (const float*)d_in[6];
    const float* b1         = (const float*)d_in[7];
    const float* bn1_g      = (const float*)d_in[8];
    const float* bn1_b      = (const float*)d_in[9];
    const float* W2         = (const float*)d_in[10];
    const float* b2         = (const float*)d_in[11];
    const float* bn2_g      = (const float*)d_in[12];
    const float* bn2_b      = (const float*)d_in[13];
    const float* W3         = (const float*)d_in[14];
    const float* b3         = (const float*)d_in[15];
    const float* bn3_g      = (const float*)d_in[16];
    const float* bn3_b      = (const float*)d_in[17];
    const float* Wout       = (const float*)d_in[18];
    const float* bout       = (const float*)d_in[19];
    const float* dense_proj = (const float*)d_in[20];
    const float* cin_W0     = (const float*)d_in[21];
    const float* cin_W1     = (const float*)d_in[22];
    const float* cin_W2     = (const float*)d_in[23];
    const float* cin_out_W  = (const float*)d_in[24];
    const float* cin_out_b  = (const float*)d_in[25];
    float* out = (float*)d_out;

    prep_kernel<<<B, 32>>>(dense_x, discrete_x, lin_emb, emb_W,
                           dense_W, dense_b, dense_proj);

    int ttot = (K0 + 2 * K12) * F;
    wtrans_kernel<<<(ttot + 255) / 256, 256>>>(cin_W0, cin_W1, cin_W2);

    // CIN layers
    cin_gemm_kernel<NN, true,  0><<<MTOT / 64, 128>>>();
    cin_gemm_kernel<F,  false, 1><<<MTOT / 64, 128>>>();
    cin_gemm_kernel<F,  false, 2><<<MTOT / 64, 128>>>();
    psum_kernel<<<B, 128>>>();

    // DNN
    mlp_gemm_kernel<0><<<dim3(D1 / 64, B / 64), 128>>>(W1, b1, bn1_g, bn1_b);
    mlp_gemm_kernel<1><<<dim3(D2 / 64, B / 64), 128>>>(W2, b2, bn2_g, bn2_b);
    mlp_gemm_kernel<2><<<dim3(D3 / 64, B / 64), 128>>>(W3, b3, bn3_g, bn3_b);

    final_kernel<<<B, 128>>>(Wout, bout, cin_out_W, cin_out_b, out);
}

// round 10
// speedup vs baseline: 2.8092x; 2.6636x over previous
#include <cuda_runtime.h>
#include <cstdint>

// ---------------- problem constants ----------------
#define B     4096
#define NS    26
#define DNS   13
#define D     16
#define V     100000
#define F     128
#define NN    39          // N = NS + DNS
#define DIN   429         // NS*D + DNS
#define D1    1024
#define D2    512
#define D3    256
#define MTOT  (B*D)       // 65536 rows for CIN GEMMs
#define EPSBN 1e-5f

// CIN chunking: k = n*C + c, chunks of 32 k (4 mma k8-steps per chunk)
#define C0P   64                  // layer0 c padded 39->64
#define NCH0  (NN*(C0P/32))       // 78
#define NCH12 (NN*(128/32))       // 156

// ---------------- device scratch (static, allowed) ----------------
__device__ float g_x0[(size_t)MTOT * NN];        // x0: [(b,d)][n]
__device__ float g_y0[(size_t)MTOT * F];         // CIN layer outputs [(b,d)][f]
__device__ float g_y1[(size_t)MTOT * F];
__device__ float g_y2[(size_t)MTOT * F];
__device__ float g_Wr0[(size_t)NCH0  * 4096];    // W in mma-fragment order, tf32-rounded
__device__ float g_Wr1[(size_t)NCH12 * 4096];
__device__ float g_Wr2[(size_t)NCH12 * 4096];
__device__ float g_h0[(size_t)B * DIN];
__device__ float g_h1[(size_t)B * D1];
__device__ float g_h2[(size_t)B * D2];
__device__ float g_h3[(size_t)B * D3];
__device__ float g_p [(size_t)B * 3 * F];
__device__ float g_lin[B];

__device__ __forceinline__ uint32_t f2tf32(float x) {   // RN round to tf32 bits
    uint32_t r; asm("cvt.rna.tf32.f32 %0, %1;" : "=r"(r) : "f"(x)); return r;
}

// ---------------- prep: gather embeddings, build x0 / h0 / linear part ----------------
__global__ void prep_kernel(const float* __restrict__ dense_x,
                            const int*   __restrict__ disc,
                            const float* __restrict__ lin_emb,
                            const float* __restrict__ emb_W,
                            const float* __restrict__ dense_W,
                            const float* __restrict__ dense_b,
                            const float* __restrict__ dense_proj)
{
    int b = blockIdx.x;
    int lane = threadIdx.x;          // 32 threads
    float linacc = 0.f;

    if (lane < NS) {
        int idx = disc[b * NS + lane];
        const float4* src = reinterpret_cast<const float4*>(
            emb_W + ((size_t)lane * V + (size_t)idx) * D);
        float e[16];
        #pragma unroll
        for (int j = 0; j < 4; j++) {
            float4 v = src[j];
            e[4*j+0] = v.x; e[4*j+1] = v.y; e[4*j+2] = v.z; e[4*j+3] = v.w;
        }
        #pragma unroll
        for (int j = 0; j < 16; j++) {
            g_h0[(size_t)b * DIN + lane * 16 + j] = e[j];
            g_x0[((size_t)(b * D + j)) * NN + lane] = e[j];
        }
        linacc += lin_emb[(size_t)lane * V + idx];
    }
    if (lane < DNS) {
        float v = dense_x[b * DNS + lane];
        g_h0[(size_t)b * DIN + NS * D + lane] = v;
        #pragma unroll
        for (int d = 0; d < D; d++)
            g_x0[((size_t)(b * D + d)) * NN + NS + lane] = v * dense_proj[lane * D + d];
        linacc += v * dense_W[lane];
    }
    #pragma unroll
    for (int o = 16; o; o >>= 1) linacc += __shfl_down_sync(0xffffffffu, linacc, o);
    if (lane == 0) g_lin[b] = linacc + dense_b[0];
}

// ---------------- W reorder into mma-fragment order, tf32-rounded --------------------
// Chunk ch covers n = ch/(C/32), c0 = (ch mod (C/32))*32, k_local in [0,32).
// Float slot u = ((s*16 + t)*32 + lane)*2 + p holds
//   Wt[k_local = s*8 + (lane&3) + p*4][f = t*8 + (lane>>2)]
// so the hot loop reads one conflict-free LDS.64 per (s,t,lane): {b0,b1} fragment.
__global__ void prep_w_kernel(const float* __restrict__ W0,
                              const float* __restrict__ W1,
                              const float* __restrict__ W2)
{
    int idx = blockIdx.x * 256 + threadIdx.x;
    const int S0 = NCH0 * 4096, S12 = NCH12 * 4096;
    float* dst; const float* W; int C, rem, isL0 = 0;
    if (idx < S0)              { dst = g_Wr0; rem = idx;            C = C0P; W = W0; isL0 = 1; }
    else if (idx < S0 + S12)   { dst = g_Wr1; rem = idx - S0;       C = 128; W = W1; }
    else if (idx < S0 + 2*S12) { dst = g_Wr2; rem = idx - S0 - S12; C = 128; W = W2; }
    else return;

    int ch = rem >> 12, u = rem & 4095;
    int s    = u >> 10;
    int t    = (u >> 6) & 15;
    int lane = (u >> 1) & 31;
    int p    = u & 1;
    int kl = s * 8 + (lane & 3) + p * 4;
    int f  = t * 8 + (lane >> 2);
    int n  = ch / (C / 32);
    int c  = (ch % (C / 32)) * 32 + kl;
    float v;
    if (isL0) v = (c < NN) ? W[(f * NN + c) * NN + n] : 0.f;
    else      v = W[(f * 128 + c) * NN + n];
    dst[rem] = __uint_as_float(f2tf32(v));
}

// ---------------- CIN layer via mma.sync tf32 (base sm_103 ISA) ----------------------
// y[m][f] = sum_k Z[m][k]*Wt[f][k], k = n*C + c, Z[m][n*C+c] = x0[m][n]*xj[m][c].
// CTA: 128 m-rows x 128 f. 8 warps; warp w owns rows [16w,16w+16), all 128 f.
template<int L>
__global__ void __launch_bounds__(256, 1)
cin_mma_kernel()
{
    constexpr int C    = (L == 0) ? C0P : 128;
    constexpr int NCHK = NN * (C / 32);
    constexpr int XJS  = C + 4;                  // padded row stride (68/132: %32==4 -> conflict-free)
    constexpr int CDIV = C / 32;

    extern __shared__ char smem[];
    float* wbuf = (float*)smem;                  // 2 x 4096 floats (double buffer)
    float* xj_s = (float*)(smem + 32768);        // [128][XJS]
    float* x0c  = xj_s + 128 * XJS;              // [NN][128] column-major

    const float* __restrict__ Wr = (L == 0) ? g_Wr0 : (L == 1) ? g_Wr1 : g_Wr2;
    float* __restrict__ y        = (L == 0) ? g_y0  : (L == 1) ? g_y1  : g_y2;
    const float* __restrict__ xjsrc = (L == 1) ? g_y0 : g_y1;    // unused for L==0

    int tid = threadIdx.x, m0 = blockIdx.x * 128;
    int wm = tid >> 5, lane = tid & 31, gid = lane >> 2, qid = lane & 3;

    // stage xj (row-major, padded) and x0 column-major
    if (L == 0) {
        for (int i = tid; i < 128 * C0P; i += 256) {
            int r = i >> 6, c = i & 63;
            xj_s[r * XJS + c] = (c < NN) ? g_x0[(size_t)(m0 + r) * NN + c] : 0.f;
        }
    } else {
        for (int i = tid; i < 128 * 32; i += 256) {
            int r = i >> 5, q = i & 31;
            *(float4*)(xj_s + r * XJS + q * 4) =
                *(const float4*)(xjsrc + (size_t)(m0 + r) * F + q * 4);
        }
    }
    for (int i = tid; i < NN * 128; i += 256) {
        int n = i >> 7, m = i & 127;
        x0c[i] = g_x0[(size_t)(m0 + m) * NN + n];
    }

    // prefetch W chunk 0 into registers
    float4 pf[4];
    {
        const float4* wg = (const float4*)Wr;
        #pragma unroll
        for (int i = 0; i < 4; i++) pf[i] = wg[tid + i * 256];
    }

    float acc[16][4];
    #pragma unroll
    for (int t = 0; t < 16; t++)
        #pragma unroll
        for (int q = 0; q < 4; q++) acc[t][q] = 0.f;

    const float* xr0b = xj_s + (wm * 16 + gid) * XJS + qid;
    const float* xr1b = xr0b + 8 * XJS;

    for (int ch = 0; ch < NCHK; ch++) {
        int st = ch & 1;
        float* wb = wbuf + st * 4096;
        #pragma unroll
        for (int i = 0; i < 4; i++) ((float4*)wb)[tid + i * 256] = pf[i];
        __syncthreads();
        if (ch + 1 < NCHK) {
            const float4* wg = (const float4*)(Wr + (size_t)(ch + 1) * 4096);
            #pragma unroll
            for (int i = 0; i < 4; i++) pf[i] = wg[tid + i * 256];
        }

        int n  = ch / CDIV;
        int c0 = (ch % CDIV) * 32;
        float x0v0 = x0c[n * 128 + wm * 16 + gid];
        float x0v1 = x0c[n * 128 + wm * 16 + gid + 8];
        const float* xr0 = xr0b + c0;
        const float* xr1 = xr1b + c0;
        const uint2* wfr = (const uint2*)wb;

        #pragma unroll
        for (int s = 0; s < 4; s++) {
            uint32_t a0 = f2tf32(x0v0 * xr0[s * 8]);
            uint32_t a1 = f2tf32(x0v1 * xr1[s * 8]);
            uint32_t a2 = f2tf32(x0v0 * xr0[s * 8 + 4]);
            uint32_t a3 = f2tf32(x0v1 * xr1[s * 8 + 4]);
            #pragma unroll
            for (int t = 0; t < 16; t++) {
                uint2 b = wfr[(s * 16 + t) * 32 + lane];
                asm volatile(
                    "mma.sync.aligned.m16n8k8.row.col.f32.tf32.tf32.f32 "
                    "{%0,%1,%2,%3}, {%4,%5,%6,%7}, {%8,%9}, {%0,%1,%2,%3};"
                    : "+f"(acc[t][0]), "+f"(acc[t][1]), "+f"(acc[t][2]), "+f"(acc[t][3])
                    : "r"(a0), "r"(a1), "r"(a2), "r"(a3), "r"(b.x), "r"(b.y));
            }
        }
    }

    // epilogue: D fragment rows (gid, gid+8), cols 2*qid,2*qid+1 per 8-col tile
    int r0 = m0 + wm * 16 + gid;
    #pragma unroll
    for (int t = 0; t < 16; t++) {
        float2 lo = make_float2(acc[t][0], acc[t][1]);
        float2 hi = make_float2(acc[t][2], acc[t][3]);
        *(float2*)(y + (size_t)r0 * F + t * 8 + 2 * qid)       = lo;
        *(float2*)(y + (size_t)(r0 + 8) * F + t * 8 + 2 * qid) = hi;
    }
}

// ---------------- p sums: p_l[b][f] = sum_d y_l[(b,d)][f] ----------------
__global__ void psum_kernel()
{
    int b = blockIdx.x, f = threadIdx.x;     // 128 threads
    float s0 = 0.f, s1 = 0.f, s2 = 0.f;
    #pragma unroll
    for (int d = 0; d < D; d++) {
        size_t idx = (size_t)(b * D + d) * F + f;
        s0 += g_y0[idx]; s1 += g_y1[idx]; s2 += g_y2[idx];
    }
    g_p[(size_t)b * (3 * F) + f]           = s0;
    g_p[(size_t)b * (3 * F) + F + f]       = s1;
    g_p[(size_t)b * (3 * F) + 2 * F + f]   = s2;
}

// ---------------- MLP GEMM + bias + BN(eval) + ReLU ----------------
template<int STAGE>
__global__ void __launch_bounds__(128)
mlp_gemm_kernel(const float* __restrict__ W, const float* __restrict__ bias,
                const float* __restrict__ bng, const float* __restrict__ bnb)
{
    constexpr int K  = (STAGE == 0) ? DIN : (STAGE == 1) ? D1 : D2;
    constexpr int NO = (STAGE == 0) ? D1  : (STAGE == 1) ? D2 : D3;
    const float* __restrict__ A = (STAGE == 0) ? g_h0 : (STAGE == 1) ? g_h1 : g_h2;
    float* __restrict__ O       = (STAGE == 0) ? g_h1 : (STAGE == 1) ? g_h2 : g_h3;

    constexpr int RS = 68;
    __shared__ float AT[32 * RS];
    __shared__ float Wc[32 * 64];

    int m0 = blockIdx.y * 64, n0 = blockIdx.x * 64;
    int tid = threadIdx.x, tx = tid & 15, ty = tid >> 4;

    float acc[8][4];
    #pragma unroll
    for (int r = 0; r < 8; r++)
        #pragma unroll
        for (int f = 0; f < 4; f++) acc[r][f] = 0.f;

    for (int k0 = 0; k0 < K; k0 += 32) {
        for (int i = tid; i < 64 * 32; i += 128) {
            int r = i >> 5, k = i & 31;
            AT[k * RS + r] = (k0 + k < K) ? A[(size_t)(m0 + r) * K + k0 + k] : 0.f;
        }
        for (int i = tid; i < 32 * 64; i += 128) {
            int k = i >> 6, n = i & 63;
            Wc[k * 64 + n] = (k0 + k < K) ? W[(size_t)(k0 + k) * NO + n0 + n] : 0.f;
        }
        __syncthreads();

        #pragma unroll 4
        for (int k = 0; k < 32; k++) {
            float av[8];
            const float* ap = &AT[k * RS + ty * 8];
            #pragma unroll
            for (int r = 0; r < 8; r++) av[r] = ap[r];
            float4 w = *reinterpret_cast<const float4*>(&Wc[k * 64 + tx * 4]);
            float wv[4] = {w.x, w.y, w.z, w.w};
            #pragma unroll
            for (int r = 0; r < 8; r++)
                #pragma unroll
                for (int f = 0; f < 4; f++) acc[r][f] += av[r] * wv[f];
        }
        __syncthreads();
    }

    float rs = rsqrtf(1.f + EPSBN);
    int nb = n0 + tx * 4;
    float4 bi = *reinterpret_cast<const float4*>(&bias[nb]);
    float4 gg = *reinterpret_cast<const float4*>(&bng[nb]);
    float4 sh = *reinterpret_cast<const float4*>(&bnb[nb]);
    float s0 = gg.x * rs, s1 = gg.y * rs, s2 = gg.z * rs, s3 = gg.w * rs;

    #pragma unroll
    for (int r = 0; r < 8; r++) {
        int m = m0 + ty * 8 + r;
        float4 o;
        o.x = fmaxf(0.f, (acc[r][0] + bi.x) * s0 + sh.x);
        o.y = fmaxf(0.f, (acc[r][1] + bi.y) * s1 + sh.y);
        o.z = fmaxf(0.f, (acc[r][2] + bi.z) * s2 + sh.z);
        o.w = fmaxf(0.f, (acc[r][3] + bi.w) * s3 + sh.w);
        *reinterpret_cast<float4*>(&O[(size_t)m * NO + nb]) = o;
    }
}

// ---------------- final combine ----------------
__global__ void final_kernel(const float* __restrict__ Wout, const float* __restrict__ bout,
                             const float* __restrict__ cW,   const float* __restrict__ cb,
                             float* __restrict__ out)
{
    int b = blockIdx.x, tid = threadIdx.x;      // 128 threads
    float acc = 0.f;
    for (int i = tid; i < D3; i += 128)     acc += g_h3[(size_t)b * D3 + i] * Wout[i];
    for (int i = tid; i < 3 * F; i += 128)  acc += g_p[(size_t)b * (3 * F) + i] * cW[i];
    __shared__ float sm[4];
    #pragma unroll
    for (int o = 16; o; o >>= 1) acc += __shfl_down_sync(0xffffffffu, acc, o);
    if ((tid & 31) == 0) sm[tid >> 5] = acc;
    __syncthreads();
    if (tid == 0)
        out[b] = sm[0] + sm[1] + sm[2] + sm[3] + g_lin[b] + bout[0] + cb[0];
}

// ---------------- launch ----------------
extern "C" void kernel_launch(void* const* d_in, const int* in_sizes, int n_in,
                              void* d_out, int out_size)
{
    const float* dense_x    = (const float*)d_in[0];
    const int*   discrete_x = (const int*)  d_in[1];
    const float* lin_emb    = (const float*)d_in[2];
    const float* emb_W      = (const float*)d_in[3];
    const float* dense_W    = (const float*)d_in[4];
    const float* dense_b    = (const float*)d_in[5];
    const float* W1         = (const float*)d_in[6];
    const float* b1         = (const float*)d_in[7];
    const float* bn1_g      = (const float*)d_in[8];
    const float* bn1_b      = (const float*)d_in[9];
    const float* W2         = (const float*)d_in[10];
    const float* b2         = (const float*)d_in[11];
    const float* bn2_g      = (const float*)d_in[12];
    const float* bn2_b      = (const float*)d_in[13];
    const float* W3         = (const float*)d_in[14];
    const float* b3         = (const float*)d_in[15];
    const float* bn3_g      = (const float*)d_in[16];
    const float* bn3_b      = (const float*)d_in[17];
    const float* Wout       = (const float*)d_in[18];
    const float* bout       = (const float*)d_in[19];
    const float* dense_proj = (const float*)d_in[20];
    const float* cin_W0     = (const float*)d_in[21];
    const float* cin_W1     = (const float*)d_in[22];
    const float* cin_W2     = (const float*)d_in[23];
    const float* cin_out_W  = (const float*)d_in[24];
    const float* cin_out_b  = (const float*)d_in[25];
    float* out = (float*)d_out;

    // dynamic smem: W double-buffer 32KB + xj[128][C+4] + x0c[NN][128]
    const int smem0  = 32768 + 128 * (C0P + 4) * 4 + NN * 128 * 4;   // 87552
    const int smem12 = 32768 + 128 * (128 + 4) * 4 + NN * 128 * 4;   // 120320
    cudaFuncSetAttribute(cin_mma_kernel<0>, cudaFuncAttributeMaxDynamicSharedMemorySize, smem0);
    cudaFuncSetAttribute(cin_mma_kernel<1>, cudaFuncAttributeMaxDynamicSharedMemorySize, smem12);
    cudaFuncSetAttribute(cin_mma_kernel<2>, cudaFuncAttributeMaxDynamicSharedMemorySize, smem12);

    prep_kernel<<<B, 32>>>(dense_x, discrete_x, lin_emb, emb_W,
                           dense_W, dense_b, dense_proj);

    int wtot = (NCH0 + 2 * NCH12) * 4096;
    prep_w_kernel<<<(wtot + 255) / 256, 256>>>(cin_W0, cin_W1, cin_W2);

    // CIN layers on tensor cores (mma.sync tf32)
    cin_mma_kernel<0><<<MTOT / 128, 256, smem0>>>();
    cin_mma_kernel<1><<<MTOT / 128, 256, smem12>>>();
    cin_mma_kernel<2><<<MTOT / 128, 256, smem12>>>();
    psum_kernel<<<B, 128>>>();

    // DNN
    mlp_gemm_kernel<0><<<dim3(D1 / 64, B / 64), 128>>>(W1, b1, bn1_g, bn1_b);
    mlp_gemm_kernel<1><<<dim3(D2 / 64, B / 64), 128>>>(W2, b2, bn2_g, bn2_b);
    mlp_gemm_kernel<2><<<dim3(D3 / 64, B / 64), 128>>>(W3, b3, bn3_g, bn3_b);

    final_kernel<<<B, 128>>>(Wout, bout, cin_out_W, cin_out_b, out);
}